// round 8
// baseline (speedup 1.0000x reference)
#include <cuda_runtime.h>
#include <cuda_fp16.h>
#include <cstdint>

#define TPB 512

// smem byte offsets
#define OF_WC   0u           // 32KB fp16 Wcf (128 rows x 256B, swizzled)
#define OF_WF   32768u       // 32KB fp16 Wfc
#define OF_WD   65536u       // 8KB fp16 Wdf (init-only; he buf0 overlays after hoist)
#define OF_HEq(b,q)  (65536u + (uint32_t)(b) * 8192u + (uint32_t)(q) * 2048u)
#define OF_SRCq(b,q) (81920u + (uint32_t)(b) * 32768u + (uint32_t)(q) * 8192u)
#define OF_SG(q)     (147456u + (uint32_t)(q) * 16384u)  // fp32 staging src
#define OF_SGH(q)    (212992u + (uint32_t)(q) * 4096u)   // fp32 staging he
#define OF_BC   229376u
#define OF_BD   229888u
#define OF_BF   230400u
#define OF_MB   230912u      // 4 x 8B mbarriers
#define SMEM_BYTES 230976u

__device__ __forceinline__ void ldsm4(uint32_t r[4], uint32_t a) {
    asm volatile("ldmatrix.sync.aligned.m8n8.x4.shared.b16 {%0,%1,%2,%3}, [%4];"
                 : "=r"(r[0]), "=r"(r[1]), "=r"(r[2]), "=r"(r[3]) : "r"(a));
}

__device__ __forceinline__ void stsm4(uint32_t a, uint32_t r0, uint32_t r1,
                                      uint32_t r2, uint32_t r3) {
    asm volatile("stmatrix.sync.aligned.m8n8.x4.shared.b16 [%0], {%1,%2,%3,%4};"
                 :: "r"(a), "r"(r0), "r"(r1), "r"(r2), "r"(r3) : "memory");
}

__device__ __forceinline__ void mma16(float* c, const uint32_t* a, uint32_t b0, uint32_t b1) {
    asm volatile(
        "mma.sync.aligned.m16n8k16.row.col.f32.f16.f16.f32 "
        "{%0,%1,%2,%3}, {%4,%5,%6,%7}, {%8,%9}, {%0,%1,%2,%3};\n"
        : "+f"(c[0]), "+f"(c[1]), "+f"(c[2]), "+f"(c[3])
        : "r"(a[0]), "r"(a[1]), "r"(a[2]), "r"(a[3]), "r"(b0), "r"(b1));
}

__device__ __forceinline__ float ftanh(float x) {
    float e, r;
    asm("ex2.approx.f32 %0, %1;" : "=f"(e) : "f"(x * 2.8853900817779268f));
    asm("rcp.approx.f32 %0, %1;" : "=f"(r) : "f"(e + 1.0f));
    return fmaf(-2.0f, r, 1.0f);
}

__device__ __forceinline__ uint32_t pack2(float a, float b) {
    __half2 h = __floats2half2_rn(a, b);
    return *(uint32_t*)&h;
}

__device__ __forceinline__ void qbar(int quad) {
    asm volatile("bar.sync %0, 128;" :: "r"(quad + 1) : "memory");
}

__device__ __forceinline__ void mb_init(uint32_t mbar, uint32_t cnt) {
    asm volatile("mbarrier.init.shared.b64 [%0], %1;" :: "r"(mbar), "r"(cnt) : "memory");
}
__device__ __forceinline__ void mb_expect(uint32_t mbar, uint32_t tx) {
    asm volatile("mbarrier.arrive.expect_tx.shared.b64 _, [%0], %1;"
                 :: "r"(mbar), "r"(tx) : "memory");
}
__device__ __forceinline__ void mb_wait(uint32_t mbar, uint32_t parity) {
    asm volatile("{\n\t.reg .pred P1;\n\t"
        "W_%=:\n\t"
        "mbarrier.try_wait.parity.acquire.cta.shared::cta.b64 P1, [%0], %1, 0x989680;\n\t"
        "@P1 bra.uni D_%=;\n\t"
        "bra.uni W_%=;\n\t"
        "D_%=:\n\t}"
        :: "r"(mbar), "r"(parity) : "memory");
}
__device__ __forceinline__ void bulk_g2s(uint32_t dst, const void* src,
                                         uint32_t bytes, uint32_t mbar) {
    asm volatile("cp.async.bulk.shared::cta.global.mbarrier::complete_tx::bytes "
                 "[%0], [%1], %2, [%3];"
                 :: "r"(dst), "l"(src), "r"(bytes), "r"(mbar) : "memory");
}
#define PROXY_FENCE() asm volatile("fence.proxy.async.shared::cta;" ::: "memory")

// 256B-row swizzled addr (128 fp16 cols): ch 0..15
__device__ __forceinline__ uint32_t a16(uint32_t row, uint32_t ch) {
    return row * 256u + ((ch ^ (row & 7u)) << 4);
}
// 64B-row swizzled addr (32 fp16 cols): ch 0..3
__device__ __forceinline__ uint32_t h16(uint32_t row, uint32_t ch) {
    return row * 64u + ((ch ^ ((row >> 1) & 3u)) << 4);
}

__global__ void __launch_bounds__(TPB, 1)
dtnn_kernel(const float* __restrict__ gsrc, const float* __restrict__ ghe,
            const float* __restrict__ Wcf,  const float* __restrict__ bcf,
            const float* __restrict__ Wdf,  const float* __restrict__ bdf,
            const float* __restrict__ Wfc,  const float* __restrict__ bfc,
            float* __restrict__ out, int ntiles)
{
    extern __shared__ __align__(1024) unsigned char sm[];
    uint32_t smb;
    asm("{.reg .u64 t; cvta.to.shared.u64 t, %1; cvt.u32.u64 %0, t;}"
        : "=r"(smb) : "l"(sm));

    float* bC = (float*)(sm + OF_BC);
    float* bD = (float*)(sm + OF_BD);
    float* bF = (float*)(sm + OF_BF);

    const int tid  = threadIdx.x;
    const int lane = tid & 31;
    const int wid  = tid >> 5;
    const int tg   = lane & 3;
    const int quad = wid >> 2;            // node within tile; owns rows [32q,32q+32)
    const int qtid = tid & 127;
    const int n0   = (wid & 3) * 32;      // column quarter
    const uint32_t mbar = smb + OF_MB + (uint32_t)quad * 8u;
    const int grid = gridDim.x;

    // ---- mbarrier init ----
    if (tid < 4) {
        mb_init(smb + OF_MB + (uint32_t)tid * 8u, 1u);
        PROXY_FENCE();
    }
    __syncthreads();

    // ---- bulk-prefetch tile0 slice ----
    if (qtid == 0) {
        mb_expect(mbar, 20480u);
        bulk_g2s(smb + OF_SG(quad), gsrc + (size_t)blockIdx.x * 16384 + quad * 4096,
                 16384u, mbar);
        bulk_g2s(smb + OF_SGH(quad), ghe + (size_t)blockIdx.x * 4096 + quad * 1024,
                 4096u, mbar);
    }

    // ---- one-time weight + bias staging ----
    for (int i = tid; i < 2048; i += TPB) {
        int row = i >> 4, ch = i & 15;
        float4 u = ((const float4*)Wcf)[row * 32 + ch * 2];
        float4 v = ((const float4*)Wcf)[row * 32 + ch * 2 + 1];
        uint4 w = {pack2(u.x, u.y), pack2(u.z, u.w), pack2(v.x, v.y), pack2(v.z, v.w)};
        *(uint4*)(sm + OF_WC + a16(row, ch)) = w;
        u = ((const float4*)Wfc)[row * 32 + ch * 2];
        v = ((const float4*)Wfc)[row * 32 + ch * 2 + 1];
        uint4 w2 = {pack2(u.x, u.y), pack2(u.z, u.w), pack2(v.x, v.y), pack2(v.z, v.w)};
        *(uint4*)(sm + OF_WF + a16(row, ch)) = w2;
    }
    for (int i = tid; i < 512; i += TPB) {
        int row = i >> 2, ch = i & 3;
        float4 u = ((const float4*)Wdf)[row * 8 + ch * 2];
        float4 v = ((const float4*)Wdf)[row * 8 + ch * 2 + 1];
        uint4 w = {pack2(u.x, u.y), pack2(u.z, u.w), pack2(v.x, v.y), pack2(v.z, v.w)};
        *(uint4*)(sm + OF_WD + h16(row, ch)) = w;
    }
    if (tid < 128) { bC[tid] = bcf[tid]; bD[tid] = bdf[tid]; bF[tid] = bfc[tid]; }
    __syncthreads();

    // ---- per-lane ldmatrix constants ----
    const uint32_t mrow = (uint32_t)((lane & 7) | (((lane >> 3) & 1) << 3));
    const uint32_t ksel = (uint32_t)((lane >> 4) & 1);
    const uint32_t key8 = mrow & 7u;
    const uint32_t keyh = (mrow >> 1) & 3u;

    const uint32_t aBase = smb + 81920u + (uint32_t)quad * 8192u + mrow * 256u;
    const uint32_t hBase = smb + 65536u + (uint32_t)quad * 2048u + mrow * 64u;
    uint32_t wcB[2], wfB[2];
    uint32_t wdr[2][2][4];   // hoisted Wdf fragments [kt][p][4]
    {
        uint32_t wdB[2];
        #pragma unroll
        for (int p = 0; p < 2; p++) {
            uint32_t rB = (uint32_t)(n0 + 16 * p) + mrow;
            wcB[p] = smb + OF_WC + rB * 256u;
            wfB[p] = smb + OF_WF + rB * 256u;
            wdB[p] = smb + OF_WD + rB * 64u;
        }
        #pragma unroll
        for (int kt = 0; kt < 2; kt++) {
            uint32_t ub = ((2u * kt + ksel) ^ keyh) << 4;
            ldsm4(wdr[kt][0], wdB[0] + ub);
            ldsm4(wdr[kt][1], wdB[1] + ub);
        }
    }
    const uint32_t srow = (uint32_t)(((lane >> 4) & 1) * 16 + ((lane >> 3) & 1) * 8
                                     + (lane & 7));

    __syncthreads();   // WD reads done before he-buf0 overlays it

    // ---- prologue: convert tile0 -> buf0, then bulk tile0+grid ----
    uint32_t ph = 0;
    mb_wait(mbar, ph); ph ^= 1;
    {
        const float4* sg = (const float4*)(sm + OF_SG(quad));
        #pragma unroll
        for (int it = 0; it < 4; it++) {
            int i = qtid + it * 128;
            int row = i >> 4, ch = i & 15;
            float4 u = sg[row * 32 + ch * 2];
            float4 v = sg[row * 32 + ch * 2 + 1];
            uint4 w = {pack2(u.x, u.y), pack2(u.z, u.w),
                       pack2(v.x, v.y), pack2(v.z, v.w)};
            *(uint4*)(sm + OF_SRCq(0, quad) + a16((uint32_t)row, (uint32_t)ch)) = w;
        }
        const float4* sh = (const float4*)(sm + OF_SGH(quad));
        {
            int i = qtid;
            int row = i >> 2, ch = i & 3;
            float4 u = sh[row * 8 + ch * 2];
            float4 v = sh[row * 8 + ch * 2 + 1];
            uint4 w = {pack2(u.x, u.y), pack2(u.z, u.w),
                       pack2(v.x, v.y), pack2(v.z, v.w)};
            *(uint4*)(sm + OF_HEq(0, quad) + h16((uint32_t)row, (uint32_t)ch)) = w;
        }
    }
    qbar(quad);
    if (qtid == 0 && blockIdx.x + grid < ntiles) {
        int nt_ = blockIdx.x + grid;
        PROXY_FENCE();
        mb_expect(mbar, 20480u);
        bulk_g2s(smb + OF_SG(quad), gsrc + (size_t)nt_ * 16384 + quad * 4096,
                 16384u, mbar);
        bulk_g2s(smb + OF_SGH(quad), ghe + (size_t)nt_ * 4096 + quad * 1024,
                 4096u, mbar);
    }

    int cur = 0;
    for (int tile = blockIdx.x; tile < ntiles; tile += grid, cur ^= 1) {
        const uint32_t aB0 = aBase + (uint32_t)cur * 32768u;
        const uint32_t aB1 = aB0 + 16u * 256u;
        const uint32_t hB0 = hBase + (uint32_t)cur * 8192u;
        const uint32_t hB1 = hB0 + 16u * 64u;

        // GEMM2: accE = he @ Wdf^T (hoisted B)
        float accE[2][2][4];
        #pragma unroll
        for (int mt = 0; mt < 2; mt++)
            #pragma unroll
            for (int nt = 0; nt < 2; nt++)
                accE[mt][nt][0] = accE[mt][nt][1] = accE[mt][nt][2] = accE[mt][nt][3] = 0.f;
        float accE2[2][2][4];
        #pragma unroll
        for (int mt = 0; mt < 2; mt++)
            #pragma unroll
            for (int nt = 0; nt < 2; nt++)
                accE2[mt][nt][0] = accE2[mt][nt][1] = accE2[mt][nt][2] = accE2[mt][nt][3] = 0.f;
        #pragma unroll
        for (int kt = 0; kt < 2; kt++) {
            uint32_t A0[4], A1[4];
            uint32_t ua = ((2u * kt + ksel) ^ keyh) << 4;
            ldsm4(A0, hB0 + ua);
            ldsm4(A1, hB1 + ua);
            mma16(accE[0][0],  A0, wdr[kt][0][0], wdr[kt][0][2]);
            mma16(accE[0][1],  A0, wdr[kt][0][1], wdr[kt][0][3]);
            mma16(accE[1][0],  A1, wdr[kt][0][0], wdr[kt][0][2]);
            mma16(accE[1][1],  A1, wdr[kt][0][1], wdr[kt][0][3]);
            mma16(accE2[0][0], A0, wdr[kt][1][0], wdr[kt][1][2]);
            mma16(accE2[0][1], A0, wdr[kt][1][1], wdr[kt][1][3]);
            mma16(accE2[1][0], A1, wdr[kt][1][0], wdr[kt][1][2]);
            mma16(accE2[1][1], A1, wdr[kt][1][1], wdr[kt][1][3]);
        }

        // GEMM1: accC = src @ Wcf^T
        float accC[2][4][4];
        #pragma unroll
        for (int mt = 0; mt < 2; mt++)
            #pragma unroll
            for (int nt = 0; nt < 4; nt++)
                accC[mt][nt][0] = accC[mt][nt][1] = accC[mt][nt][2] = accC[mt][nt][3] = 0.f;
        #pragma unroll
        for (int kt = 0; kt < 8; kt++) {
            uint32_t A0[4], A1[4], B[2][4];
            uint32_t ua = ((2u * kt + ksel) ^ key8) << 4;
            ldsm4(A0, aB0 + ua);
            ldsm4(A1, aB1 + ua);
            #pragma unroll
            for (int p = 0; p < 2; p++) ldsm4(B[p], wcB[p] + ua);
            #pragma unroll
            for (int p = 0; p < 2; p++) {
                mma16(accC[0][2 * p],     A0, B[p][0], B[p][2]);
                mma16(accC[0][2 * p + 1], A0, B[p][1], B[p][3]);
                mma16(accC[1][2 * p],     A1, B[p][0], B[p][2]);
                mma16(accC[1][2 * p + 1], A1, B[p][1], B[p][3]);
            }
        }

        // gate (writes h over src[cur])
        qbar(quad);
        #pragma unroll
        for (int nt = 0; nt < 4; nt++) {
            int c = n0 + nt * 8 + 2 * tg;
            float2 bc2 = *(float2*)(bC + c);
            float2 bd2 = *(float2*)(bD + c);
            const float* e0 = (nt < 2) ? accE[0][nt] : accE2[0][nt - 2];
            const float* e1 = (nt < 2) ? accE[1][nt] : accE2[1][nt - 2];
            uint32_t p0 = pack2((accC[0][nt][0] + bc2.x) * (e0[0] + bd2.x),
                                (accC[0][nt][1] + bc2.y) * (e0[1] + bd2.y));
            uint32_t p1 = pack2((accC[0][nt][2] + bc2.x) * (e0[2] + bd2.x),
                                (accC[0][nt][3] + bc2.y) * (e0[3] + bd2.y));
            uint32_t p2 = pack2((accC[1][nt][0] + bc2.x) * (e1[0] + bd2.x),
                                (accC[1][nt][1] + bc2.y) * (e1[1] + bd2.y));
            uint32_t p3 = pack2((accC[1][nt][2] + bc2.x) * (e1[2] + bd2.x),
                                (accC[1][nt][3] + bc2.y) * (e1[3] + bd2.y));
            uint32_t ch = (uint32_t)(n0 >> 3) + (uint32_t)nt;
            stsm4(smb + OF_SRCq(cur, quad) + a16(srow, ch), p0, p1, p2, p3);
        }
        qbar(quad);

        // GEMM3: accO = h @ Wfc^T (reuse accC)
        #pragma unroll
        for (int mt = 0; mt < 2; mt++)
            #pragma unroll
            for (int nt = 0; nt < 4; nt++)
                accC[mt][nt][0] = accC[mt][nt][1] = accC[mt][nt][2] = accC[mt][nt][3] = 0.f;
        #pragma unroll
        for (int kt = 0; kt < 8; kt++) {
            uint32_t A0[4], A1[4], B[2][4];
            uint32_t ua = ((2u * kt + ksel) ^ key8) << 4;
            ldsm4(A0, aB0 + ua);
            ldsm4(A1, aB1 + ua);
            #pragma unroll
            for (int p = 0; p < 2; p++) ldsm4(B[p], wfB[p] + ua);
            #pragma unroll
            for (int p = 0; p < 2; p++) {
                mma16(accC[0][2 * p],     A0, B[p][0], B[p][2]);
                mma16(accC[0][2 * p + 1], A0, B[p][1], B[p][3]);
                mma16(accC[1][2 * p],     A1, B[p][0], B[p][2]);
                mma16(accC[1][2 * p + 1], A1, B[p][1], B[p][3]);
            }
        }

        // convert next tile into the other buffer (overlaps epilogue below)
        if (tile + grid < ntiles) {
            mb_wait(mbar, ph); ph ^= 1;
            const float4* sg = (const float4*)(sm + OF_SG(quad));
            int nb = cur ^ 1;
            #pragma unroll
            for (int it = 0; it < 4; it++) {
                int i = qtid + it * 128;
                int row = i >> 4, ch = i & 15;
                float4 u = sg[row * 32 + ch * 2];
                float4 v = sg[row * 32 + ch * 2 + 1];
                uint4 w = {pack2(u.x, u.y), pack2(u.z, u.w),
                           pack2(v.x, v.y), pack2(v.z, v.w)};
                *(uint4*)(sm + OF_SRCq(nb, quad) + a16((uint32_t)row, (uint32_t)ch)) = w;
            }
            const float4* sh = (const float4*)(sm + OF_SGH(quad));
            {
                int i = qtid;
                int row = i >> 2, ch = i & 3;
                float4 u = sh[row * 8 + ch * 2];
                float4 v = sh[row * 8 + ch * 2 + 1];
                uint4 w = {pack2(u.x, u.y), pack2(u.z, u.w),
                           pack2(v.x, v.y), pack2(v.z, v.w)};
                *(uint4*)(sm + OF_HEq(nb, quad) + h16((uint32_t)row, (uint32_t)ch)) = w;
            }
            qbar(quad);  // fp16 next-tile visible; staging free
            if (qtid == 0 && tile + 2 * grid < ntiles) {
                int nt_ = tile + 2 * grid;
                PROXY_FENCE();
                mb_expect(mbar, 20480u);
                bulk_g2s(smb + OF_SG(quad), gsrc + (size_t)nt_ * 16384 + quad * 4096,
                         16384u, mbar);
                bulk_g2s(smb + OF_SGH(quad), ghe + (size_t)nt_ * 4096 + quad * 1024,
                         4096u, mbar);
            }
        }

        // epilogue: tanh + mailbox reduce (3 shuffle levels, ILP 8)
        {
            const int node = tile * 4 + quad;
            float v[8];
            #pragma unroll
            for (int nt = 0; nt < 4; nt++) {
                int c = n0 + nt * 8 + 2 * tg;
                float2 bf2 = *(float2*)(bF + c);
                v[2 * nt]     = ftanh(accC[0][nt][0] + bf2.x) + ftanh(accC[0][nt][2] + bf2.x)
                              + ftanh(accC[1][nt][0] + bf2.x) + ftanh(accC[1][nt][2] + bf2.x);
                v[2 * nt + 1] = ftanh(accC[0][nt][1] + bf2.y) + ftanh(accC[0][nt][3] + bf2.y)
                              + ftanh(accC[1][nt][1] + bf2.y) + ftanh(accC[1][nt][3] + bf2.y);
            }
            #pragma unroll
            for (int m = 4; m < 32; m <<= 1) {
                #pragma unroll
                for (int i = 0; i < 8; i++)
                    v[i] += __shfl_xor_sync(0xffffffffu, v[i], m);
            }
            if (lane < 4) {
                #pragma unroll
                for (int nt = 0; nt < 4; nt++) {
                    float2 o = {v[2 * nt], v[2 * nt + 1]};
                    *(float2*)(out + (size_t)node * 128 + n0 + nt * 8 + 2 * tg) = o;
                }
            }
        }
    }
}

extern "C" void kernel_launch(void* const* d_in, const int* in_sizes, int n_in,
                              void* d_out, int out_size)
{
    const float* src = (const float*)d_in[0];
    const float* he  = (const float*)d_in[1];
    const float* Wcf = (const float*)d_in[2];
    const float* bcf = (const float*)d_in[3];
    const float* Wdf = (const float*)d_in[4];
    const float* bdf = (const float*)d_in[5];
    const float* Wfc = (const float*)d_in[6];
    const float* bfc = (const float*)d_in[7];
    float* out = (float*)d_out;

    int ntiles = in_sizes[0] / 16384;   // 128 pairs (4 nodes) per tile

    int nsm = 148;
    cudaDeviceGetAttribute(&nsm, cudaDevAttrMultiProcessorCount, 0);
    int grid = nsm < ntiles ? nsm : ntiles;

    cudaFuncSetAttribute(dtnn_kernel, cudaFuncAttributeMaxDynamicSharedMemorySize,
                         (int)SMEM_BYTES);
    dtnn_kernel<<<grid, TPB, SMEM_BYTES>>>(src, he, Wcf, bcf, Wdf, bdf, Wfc, bfc,
                                           out, ntiles);
}

// round 9
// speedup vs baseline: 1.2060x; 1.2060x over previous
#include <cuda_runtime.h>
#include <cuda_fp16.h>
#include <cstdint>

#define TPB 512

// smem byte offsets
#define OF_WC   0u           // 32KB fp16 Wcf (128 rows x 256B, swizzled)
#define OF_WF   32768u       // 32KB fp16 Wfc
#define OF_WD   65536u       // 8KB fp16 Wdf (hoisted to regs at init)
#define OF_SRCq(q) (73728u  + (uint32_t)(q) * 8192u)   // fp16 src slice: 32x128
#define OF_HEq(q)  (106496u + (uint32_t)(q) * 2048u)   // fp16 he slice: 32x32
#define OF_Hq(q)   (114688u + (uint32_t)(q) * 8192u)   // fp16 h slice: 32x128
#define OF_SG(q)   (147456u + (uint32_t)(q) * 16384u)  // fp32 staging src
#define OF_SGH(q)  (212992u + (uint32_t)(q) * 4096u)   // fp32 staging he
#define OF_BC   229376u
#define OF_BD   229888u
#define OF_BF   230400u
#define OF_MB   230912u      // 4 x 8B mbarriers
#define SMEM_BYTES 230976u

__device__ __forceinline__ void ldsm4(uint32_t r[4], uint32_t a) {
    asm volatile("ldmatrix.sync.aligned.m8n8.x4.shared.b16 {%0,%1,%2,%3}, [%4];"
                 : "=r"(r[0]), "=r"(r[1]), "=r"(r[2]), "=r"(r[3]) : "r"(a));
}

__device__ __forceinline__ void stsm4(uint32_t a, uint32_t r0, uint32_t r1,
                                      uint32_t r2, uint32_t r3) {
    asm volatile("stmatrix.sync.aligned.m8n8.x4.shared.b16 [%0], {%1,%2,%3,%4};"
                 :: "r"(a), "r"(r0), "r"(r1), "r"(r2), "r"(r3) : "memory");
}

__device__ __forceinline__ void mma16(float* c, const uint32_t* a, uint32_t b0, uint32_t b1) {
    asm volatile(
        "mma.sync.aligned.m16n8k16.row.col.f32.f16.f16.f32 "
        "{%0,%1,%2,%3}, {%4,%5,%6,%7}, {%8,%9}, {%0,%1,%2,%3};\n"
        : "+f"(c[0]), "+f"(c[1]), "+f"(c[2]), "+f"(c[3])
        : "r"(a[0]), "r"(a[1]), "r"(a[2]), "r"(a[3]), "r"(b0), "r"(b1));
}

// HW tanh (single MUFU op, sm_75+ baseline PTX)
__device__ __forceinline__ float ftanh(float x) {
    float r;
    asm("tanh.approx.f32 %0, %1;" : "=f"(r) : "f"(x));
    return r;
}

__device__ __forceinline__ uint32_t pack2(float a, float b) {
    __half2 h = __floats2half2_rn(a, b);
    return *(uint32_t*)&h;
}

__device__ __forceinline__ void qbar(int quad) {
    asm volatile("bar.sync %0, 128;" :: "r"(quad + 1) : "memory");
}

__device__ __forceinline__ void mb_init(uint32_t mbar, uint32_t cnt) {
    asm volatile("mbarrier.init.shared.b64 [%0], %1;" :: "r"(mbar), "r"(cnt) : "memory");
}
__device__ __forceinline__ void mb_expect(uint32_t mbar, uint32_t tx) {
    asm volatile("mbarrier.arrive.expect_tx.shared.b64 _, [%0], %1;"
                 :: "r"(mbar), "r"(tx) : "memory");
}
__device__ __forceinline__ void mb_wait(uint32_t mbar, uint32_t parity) {
    asm volatile("{\n\t.reg .pred P1;\n\t"
        "W_%=:\n\t"
        "mbarrier.try_wait.parity.acquire.cta.shared::cta.b64 P1, [%0], %1, 0x989680;\n\t"
        "@P1 bra.uni D_%=;\n\t"
        "bra.uni W_%=;\n\t"
        "D_%=:\n\t}"
        :: "r"(mbar), "r"(parity) : "memory");
}
__device__ __forceinline__ void bulk_g2s(uint32_t dst, const void* src,
                                         uint32_t bytes, uint32_t mbar) {
    asm volatile("cp.async.bulk.shared::cta.global.mbarrier::complete_tx::bytes "
                 "[%0], [%1], %2, [%3];"
                 :: "r"(dst), "l"(src), "r"(bytes), "r"(mbar) : "memory");
}
#define PROXY_FENCE() asm volatile("fence.proxy.async.shared::cta;" ::: "memory")

// 256B-row swizzled addr (128 fp16 cols): ch 0..15
__device__ __forceinline__ uint32_t a16(uint32_t row, uint32_t ch) {
    return row * 256u + ((ch ^ (row & 7u)) << 4);
}
// 64B-row swizzled addr (32 fp16 cols): ch 0..3
__device__ __forceinline__ uint32_t h16(uint32_t row, uint32_t ch) {
    return row * 64u + ((ch ^ ((row >> 1) & 3u)) << 4);
}

__global__ void __launch_bounds__(TPB, 1)
dtnn_kernel(const float* __restrict__ gsrc, const float* __restrict__ ghe,
            const float* __restrict__ Wcf,  const float* __restrict__ bcf,
            const float* __restrict__ Wdf,  const float* __restrict__ bdf,
            const float* __restrict__ Wfc,  const float* __restrict__ bfc,
            float* __restrict__ out, int ntiles)
{
    extern __shared__ __align__(1024) unsigned char sm[];
    uint32_t smb;
    asm("{.reg .u64 t; cvta.to.shared.u64 t, %1; cvt.u32.u64 %0, t;}"
        : "=r"(smb) : "l"(sm));

    float* bC = (float*)(sm + OF_BC);
    float* bD = (float*)(sm + OF_BD);
    float* bF = (float*)(sm + OF_BF);

    const int tid  = threadIdx.x;
    const int lane = tid & 31;
    const int wid  = tid >> 5;
    const int tg   = lane & 3;
    const int quad = wid >> 2;            // node within tile; owns rows [32q,32q+32)
    const int qtid = tid & 127;
    const int n0   = (wid & 3) * 32;      // column quarter
    const uint32_t mbar = smb + OF_MB + (uint32_t)quad * 8u;
    const int grid = gridDim.x;

    // ---- mbarrier init ----
    if (tid < 4) {
        mb_init(smb + OF_MB + (uint32_t)tid * 8u, 1u);
        PROXY_FENCE();
    }
    __syncthreads();

    // ---- bulk-prefetch tile0 slice ----
    if (qtid == 0) {
        mb_expect(mbar, 20480u);
        bulk_g2s(smb + OF_SG(quad), gsrc + (size_t)blockIdx.x * 16384 + quad * 4096,
                 16384u, mbar);
        bulk_g2s(smb + OF_SGH(quad), ghe + (size_t)blockIdx.x * 4096 + quad * 1024,
                 4096u, mbar);
    }

    // ---- one-time weight + bias staging ----
    for (int i = tid; i < 2048; i += TPB) {
        int row = i >> 4, ch = i & 15;
        float4 u = ((const float4*)Wcf)[row * 32 + ch * 2];
        float4 v = ((const float4*)Wcf)[row * 32 + ch * 2 + 1];
        uint4 w = {pack2(u.x, u.y), pack2(u.z, u.w), pack2(v.x, v.y), pack2(v.z, v.w)};
        *(uint4*)(sm + OF_WC + a16(row, ch)) = w;
        u = ((const float4*)Wfc)[row * 32 + ch * 2];
        v = ((const float4*)Wfc)[row * 32 + ch * 2 + 1];
        uint4 w2 = {pack2(u.x, u.y), pack2(u.z, u.w), pack2(v.x, v.y), pack2(v.z, v.w)};
        *(uint4*)(sm + OF_WF + a16(row, ch)) = w2;
    }
    for (int i = tid; i < 512; i += TPB) {
        int row = i >> 2, ch = i & 3;
        float4 u = ((const float4*)Wdf)[row * 8 + ch * 2];
        float4 v = ((const float4*)Wdf)[row * 8 + ch * 2 + 1];
        uint4 w = {pack2(u.x, u.y), pack2(u.z, u.w), pack2(v.x, v.y), pack2(v.z, v.w)};
        *(uint4*)(sm + OF_WD + h16(row, ch)) = w;
    }
    if (tid < 128) { bC[tid] = bcf[tid]; bD[tid] = bdf[tid]; bF[tid] = bfc[tid]; }
    __syncthreads();

    // ---- per-lane ldmatrix constants ----
    const uint32_t mrow = (uint32_t)((lane & 7) | (((lane >> 3) & 1) << 3));
    const uint32_t ksel = (uint32_t)((lane >> 4) & 1);
    const uint32_t key8 = mrow & 7u;
    const uint32_t keyh = (mrow >> 1) & 3u;

    const uint32_t aB0 = smb + OF_SRCq(quad) + mrow * 256u;   // src A rows 0-15
    const uint32_t aB1 = aB0 + 16u * 256u;                    // src A rows 16-31
    const uint32_t gB0 = smb + OF_Hq(quad) + mrow * 256u;     // h A rows 0-15
    const uint32_t gB1 = gB0 + 16u * 256u;
    const uint32_t hB0 = smb + OF_HEq(quad) + mrow * 64u;
    const uint32_t hB1 = hB0 + 16u * 64u;
    uint32_t wcB[2], wfB[2];
    uint32_t wdr[2][2][4];   // hoisted Wdf fragments [kt][p][4]
    {
        uint32_t wdB[2];
        #pragma unroll
        for (int p = 0; p < 2; p++) {
            uint32_t rB = (uint32_t)(n0 + 16 * p) + mrow;
            wcB[p] = smb + OF_WC + rB * 256u;
            wfB[p] = smb + OF_WF + rB * 256u;
            wdB[p] = smb + OF_WD + rB * 64u;
        }
        #pragma unroll
        for (int kt = 0; kt < 2; kt++) {
            uint32_t ub = ((2u * kt + ksel) ^ keyh) << 4;
            ldsm4(wdr[kt][0], wdB[0] + ub);
            ldsm4(wdr[kt][1], wdB[1] + ub);
        }
    }
    const uint32_t srow = (uint32_t)(((lane >> 4) & 1) * 16 + ((lane >> 3) & 1) * 8
                                     + (lane & 7));

    uint32_t ph = 0;

    for (int tile = blockIdx.x; tile < ntiles; tile += grid) {
        // 1. this quad's bulk staging complete; prev tile's h/src reads done
        mb_wait(mbar, ph); ph ^= 1;
        qbar(quad);

        // 2. convert staging fp32 -> fp16 swizzled (own slice only)
        {
            const float4* sg = (const float4*)(sm + OF_SG(quad));
            #pragma unroll
            for (int it = 0; it < 4; it++) {
                int i = qtid + it * 128;           // 512 chunks
                int row = i >> 4, ch = i & 15;
                float4 u = sg[row * 32 + ch * 2];
                float4 v = sg[row * 32 + ch * 2 + 1];
                uint4 w = {pack2(u.x, u.y), pack2(u.z, u.w),
                           pack2(v.x, v.y), pack2(v.z, v.w)};
                *(uint4*)(sm + OF_SRCq(quad) + a16((uint32_t)row, (uint32_t)ch)) = w;
            }
            const float4* sh = (const float4*)(sm + OF_SGH(quad));
            {
                int i = qtid;                      // 128 chunks
                int row = i >> 2, ch = i & 3;
                float4 u = sh[row * 8 + ch * 2];
                float4 v = sh[row * 8 + ch * 2 + 1];
                uint4 w = {pack2(u.x, u.y), pack2(u.z, u.w),
                           pack2(v.x, v.y), pack2(v.z, v.w)};
                *(uint4*)(sm + OF_HEq(quad) + h16((uint32_t)row, (uint32_t)ch)) = w;
            }
        }
        qbar(quad);    // fp16 tiles visible; staging buffer free

        // 3. bulk-prefetch next tile's slice
        if (qtid == 0 && tile + grid < ntiles) {
            int nt_ = tile + grid;
            PROXY_FENCE();
            mb_expect(mbar, 20480u);
            bulk_g2s(smb + OF_SG(quad), gsrc + (size_t)nt_ * 16384 + quad * 4096,
                     16384u, mbar);
            bulk_g2s(smb + OF_SGH(quad), ghe + (size_t)nt_ * 4096 + quad * 1024,
                     4096u, mbar);
        }

        // 4a. GEMM2: accE = he @ Wdf^T (hoisted B fragments)
        float accE[2][4][4];
        #pragma unroll
        for (int mt = 0; mt < 2; mt++)
            #pragma unroll
            for (int nt = 0; nt < 4; nt++)
                accE[mt][nt][0] = accE[mt][nt][1] = accE[mt][nt][2] = accE[mt][nt][3] = 0.f;
        #pragma unroll
        for (int kt = 0; kt < 2; kt++) {
            uint32_t A0[4], A1[4];
            uint32_t ua = ((2u * kt + ksel) ^ keyh) << 4;
            ldsm4(A0, hB0 + ua);
            ldsm4(A1, hB1 + ua);
            #pragma unroll
            for (int p = 0; p < 2; p++) {
                mma16(accE[0][2 * p],     A0, wdr[kt][p][0], wdr[kt][p][2]);
                mma16(accE[0][2 * p + 1], A0, wdr[kt][p][1], wdr[kt][p][3]);
                mma16(accE[1][2 * p],     A1, wdr[kt][p][0], wdr[kt][p][2]);
                mma16(accE[1][2 * p + 1], A1, wdr[kt][p][1], wdr[kt][p][3]);
            }
        }

        // 4b. GEMM1: accC = src @ Wcf^T
        float accC[2][4][4];
        #pragma unroll
        for (int mt = 0; mt < 2; mt++)
            #pragma unroll
            for (int nt = 0; nt < 4; nt++)
                accC[mt][nt][0] = accC[mt][nt][1] = accC[mt][nt][2] = accC[mt][nt][3] = 0.f;
        #pragma unroll
        for (int kt = 0; kt < 8; kt++) {
            uint32_t A0[4], A1[4], B[2][4];
            uint32_t ua = ((2u * kt + ksel) ^ key8) << 4;
            ldsm4(A0, aB0 + ua);
            ldsm4(A1, aB1 + ua);
            #pragma unroll
            for (int p = 0; p < 2; p++) ldsm4(B[p], wcB[p] + ua);
            #pragma unroll
            for (int p = 0; p < 2; p++) {
                mma16(accC[0][2 * p],     A0, B[p][0], B[p][2]);
                mma16(accC[0][2 * p + 1], A0, B[p][1], B[p][3]);
                mma16(accC[1][2 * p],     A1, B[p][0], B[p][2]);
                mma16(accC[1][2 * p + 1], A1, B[p][1], B[p][3]);
            }
        }

        // 5. gate -> separate h buffer (no pre-barrier: prev reads ended at qbar #1)
        #pragma unroll
        for (int nt = 0; nt < 4; nt++) {
            int c = n0 + nt * 8 + 2 * tg;
            float2 bc2 = *(float2*)(bC + c);
            float2 bd2 = *(float2*)(bD + c);
            uint32_t p0 = pack2((accC[0][nt][0] + bc2.x) * (accE[0][nt][0] + bd2.x),
                                (accC[0][nt][1] + bc2.y) * (accE[0][nt][1] + bd2.y));
            uint32_t p1 = pack2((accC[0][nt][2] + bc2.x) * (accE[0][nt][2] + bd2.x),
                                (accC[0][nt][3] + bc2.y) * (accE[0][nt][3] + bd2.y));
            uint32_t p2 = pack2((accC[1][nt][0] + bc2.x) * (accE[1][nt][0] + bd2.x),
                                (accC[1][nt][1] + bc2.y) * (accE[1][nt][1] + bd2.y));
            uint32_t p3 = pack2((accC[1][nt][2] + bc2.x) * (accE[1][nt][2] + bd2.x),
                                (accC[1][nt][3] + bc2.y) * (accE[1][nt][3] + bd2.y));
            uint32_t ch = (uint32_t)(n0 >> 3) + (uint32_t)nt;
            stsm4(smb + OF_Hq(quad) + a16(srow, ch), p0, p1, p2, p3);
        }
        qbar(quad);    // h visible to all quad warps

        // 6. GEMM3: accO = h @ Wfc^T (reuse accC)
        #pragma unroll
        for (int mt = 0; mt < 2; mt++)
            #pragma unroll
            for (int nt = 0; nt < 4; nt++)
                accC[mt][nt][0] = accC[mt][nt][1] = accC[mt][nt][2] = accC[mt][nt][3] = 0.f;
        #pragma unroll
        for (int kt = 0; kt < 8; kt++) {
            uint32_t A0[4], A1[4], B[2][4];
            uint32_t ua = ((2u * kt + ksel) ^ key8) << 4;
            ldsm4(A0, gB0 + ua);
            ldsm4(A1, gB1 + ua);
            #pragma unroll
            for (int p = 0; p < 2; p++) ldsm4(B[p], wfB[p] + ua);
            #pragma unroll
            for (int p = 0; p < 2; p++) {
                mma16(accC[0][2 * p],     A0, B[p][0], B[p][2]);
                mma16(accC[0][2 * p + 1], A0, B[p][1], B[p][3]);
                mma16(accC[1][2 * p],     A1, B[p][0], B[p][2]);
                mma16(accC[1][2 * p + 1], A1, B[p][1], B[p][3]);
            }
        }

        // 7. epilogue: HW tanh + mailbox reduce (3 shuffle levels, ILP 8)
        {
            const int node = tile * 4 + quad;
            float v[8];
            #pragma unroll
            for (int nt = 0; nt < 4; nt++) {
                int c = n0 + nt * 8 + 2 * tg;
                float2 bf2 = *(float2*)(bF + c);
                v[2 * nt]     = ftanh(accC[0][nt][0] + bf2.x) + ftanh(accC[0][nt][2] + bf2.x)
                              + ftanh(accC[1][nt][0] + bf2.x) + ftanh(accC[1][nt][2] + bf2.x);
                v[2 * nt + 1] = ftanh(accC[0][nt][1] + bf2.y) + ftanh(accC[0][nt][3] + bf2.y)
                              + ftanh(accC[1][nt][1] + bf2.y) + ftanh(accC[1][nt][3] + bf2.y);
            }
            #pragma unroll
            for (int m = 4; m < 32; m <<= 1) {
                #pragma unroll
                for (int i = 0; i < 8; i++)
                    v[i] += __shfl_xor_sync(0xffffffffu, v[i], m);
            }
            if (lane < 4) {
                #pragma unroll
                for (int nt = 0; nt < 4; nt++) {
                    float2 o = {v[2 * nt], v[2 * nt + 1]};
                    *(float2*)(out + (size_t)node * 128 + n0 + nt * 8 + 2 * tg) = o;
                }
            }
        }
    }
}

extern "C" void kernel_launch(void* const* d_in, const int* in_sizes, int n_in,
                              void* d_out, int out_size)
{
    const float* src = (const float*)d_in[0];
    const float* he  = (const float*)d_in[1];
    const float* Wcf = (const float*)d_in[2];
    const float* bcf = (const float*)d_in[3];
    const float* Wdf = (const float*)d_in[4];
    const float* bdf = (const float*)d_in[5];
    const float* Wfc = (const float*)d_in[6];
    const float* bfc = (const float*)d_in[7];
    float* out = (float*)d_out;

    int ntiles = in_sizes[0] / 16384;   // 128 pairs (4 nodes) per tile

    int nsm = 148;
    cudaDeviceGetAttribute(&nsm, cudaDevAttrMultiProcessorCount, 0);
    int grid = nsm < ntiles ? nsm : ntiles;

    cudaFuncSetAttribute(dtnn_kernel, cudaFuncAttributeMaxDynamicSharedMemorySize,
                         (int)SMEM_BYTES);
    dtnn_kernel<<<grid, TPB, SMEM_BYTES>>>(src, he, Wcf, bcf, Wdf, bdf, Wfc, bfc,
                                           out, ntiles);
}